// round 7
// baseline (speedup 1.0000x reference)
#include <cuda_runtime.h>
#include <cuda_bf16.h>
#include <cstdint>

// Problem constants
#define H 64
#define B 16
#define L 512
#define OUT 2
#define V 32000
#define NPOS (2 * B * L)          // 16384 token positions
#define GRIDB 1024                // blocks for the unique-contract kernel

// Persistent device state. All zero at module load; every kernel chain
// restores the zero/neutral state before finishing, so graph replays are
// deterministic.
__device__ int   g_mark[V];           // 0/1 seen flags (cleared by kernel B)
__device__ int   g_unique[NPOS];      // compacted unique token list
__device__ int   g_ucount;            // unique count (reset by kernel D)
__device__ float g_r[V * H];          // r[tok] = sos @ M_tok   (8.2 MB)
__device__ float g_h[B * H];          // per-batch accumulators (reset by D)

// ---------------------------------------------------------------------------
// Kernel A: mark + compact unique tokens. 64 blocks x 256.
// ---------------------------------------------------------------------------
__global__ void dedup_kernel(const int* __restrict__ s1,
                             const int* __restrict__ s2)
{
    const int idx = blockIdx.x * 256 + threadIdx.x;   // 0..16383
    const int tok = (idx < B * L) ? __ldg(&s1[idx]) : __ldg(&s2[idx - B * L]);
    if (atomicExch(&g_mark[tok], 1) == 0) {
        const int p = atomicAdd(&g_ucount, 1);
        g_unique[p] = tok;
    }
}

// ---------------------------------------------------------------------------
// Kernel B: for each UNIQUE token, compute r[tok][h] = sum_w sos[w]*M[w][h].
// One token per block-iteration; 256 threads cover the full 16KB row with
// 4 x LDG.128 each (fully coalesced: a warp's loads span contiguous 512B).
//   h4 = tid & 15  -> float4 of output columns
//   wg = tid >> 4  -> rows wg, wg+16, wg+32, wg+48
// Also clears g_mark for the processed token.
// ---------------------------------------------------------------------------
__global__ __launch_bounds__(256, 8)
void contract_unique_kernel(const float4* __restrict__ embed,
                            const float* __restrict__ sos)
{
    const int tid = threadIdx.x;
    const int h4  = tid & 15;
    const int wg  = tid >> 4;
    const int warp = tid >> 5;
    const int lane = tid & 31;

    const float sw0 = __ldg(&sos[wg]);
    const float sw1 = __ldg(&sos[wg + 16]);
    const float sw2 = __ldg(&sos[wg + 32]);
    const float sw3 = __ldg(&sos[wg + 48]);

    const int n = g_ucount;            // written by dedup_kernel (prior launch)

    __shared__ float sh[8][H];

    for (int u = blockIdx.x; u < n; u += GRIDB) {
        const int tok = g_unique[u];
        const float4* M = embed + (size_t)tok * (H * H / 4);

        float4 m0 = __ldg(&M[(wg      ) * 16 + h4]);
        float4 m1 = __ldg(&M[(wg + 16) * 16 + h4]);
        float4 m2 = __ldg(&M[(wg + 32) * 16 + h4]);
        float4 m3 = __ldg(&M[(wg + 48) * 16 + h4]);

        float4 acc;
        acc.x = sw0 * m0.x; acc.y = sw0 * m0.y; acc.z = sw0 * m0.z; acc.w = sw0 * m0.w;
        acc.x = fmaf(sw1, m1.x, acc.x); acc.y = fmaf(sw1, m1.y, acc.y);
        acc.z = fmaf(sw1, m1.z, acc.z); acc.w = fmaf(sw1, m1.w, acc.w);
        acc.x = fmaf(sw2, m2.x, acc.x); acc.y = fmaf(sw2, m2.y, acc.y);
        acc.z = fmaf(sw2, m2.z, acc.z); acc.w = fmaf(sw2, m2.w, acc.w);
        acc.x = fmaf(sw3, m3.x, acc.x); acc.y = fmaf(sw3, m3.y, acc.y);
        acc.z = fmaf(sw3, m3.z, acc.z); acc.w = fmaf(sw3, m3.w, acc.w);

        // Pairwise reduce rows wg and wg^? : lane l and l+16 of a warp hold
        // the same h-columns for adjacent wg rows.
        acc.x += __shfl_down_sync(0xffffffffu, acc.x, 16);
        acc.y += __shfl_down_sync(0xffffffffu, acc.y, 16);
        acc.z += __shfl_down_sync(0xffffffffu, acc.z, 16);
        acc.w += __shfl_down_sync(0xffffffffu, acc.w, 16);

        if (lane < 16) {
            sh[warp][lane * 4 + 0] = acc.x;
            sh[warp][lane * 4 + 1] = acc.y;
            sh[warp][lane * 4 + 2] = acc.z;
            sh[warp][lane * 4 + 3] = acc.w;
        }
        __syncthreads();
        if (tid < H) {
            float s = 0.f;
            #pragma unroll
            for (int w = 0; w < 8; w++) s += sh[w][tid];
            g_r[tok * H + tid] = s;
        }
        if (tid == 0) g_mark[tok] = 0;      // restore for next replay
        __syncthreads();                    // protect sh before next iter
    }
}

// ---------------------------------------------------------------------------
// Kernel C: scatter-accumulate h[b][h] += r[tok][h] over all 1024 positions
// of each batch. 128 blocks (8 per batch) x 256 threads; each 64-thread group
// handles 32 positions (coalesced 256B g_r reads, mostly L2-hot).
// ---------------------------------------------------------------------------
__global__ __launch_bounds__(256, 8)
void scatter_kernel(const int* __restrict__ s1,
                    const int* __restrict__ s2)
{
    const int b = blockIdx.x >> 3;
    const int c = blockIdx.x & 7;
    const int g = threadIdx.x >> 6;
    const int h = threadIdx.x & 63;
    const int p0 = c * 128 + g * 32;       // positions p0 .. p0+31 in [0,1024)

    float acc = 0.f;
    #pragma unroll 8
    for (int p = p0; p < p0 + 32; p++) {
        const int tok = (p < L) ? __ldg(&s1[b * L + p])
                                : __ldg(&s2[b * L + (p - L)]);
        acc += __ldg(&g_r[tok * H + h]);
    }

    __shared__ float sacc[4][H];
    sacc[g][h] = acc;
    __syncthreads();
    if (threadIdx.x < H) {
        const float s = sacc[0][threadIdx.x] + sacc[1][threadIdx.x]
                      + sacc[2][threadIdx.x] + sacc[3][threadIdx.x];
        atomicAdd(&g_h[b * H + threadIdx.x], s);
    }
}

// ---------------------------------------------------------------------------
// Kernel D: tiny MLP, warp-cooperative (no big smem staging).
// Warp w handles hidden rows {w, w+32}; coalesced w1 row loads into regs,
// shuffle reductions across lanes (independent chains over b -> ILP).
// Also resets g_h and g_ucount for the next graph replay.
// ---------------------------------------------------------------------------
__global__ __launch_bounds__(1024, 1)
void mlp_kernel(const float* __restrict__ w1,
                const float* __restrict__ b1,
                const float* __restrict__ w2,
                const float* __restrict__ b2,
                float* __restrict__ out)
{
    __shared__ float hs[B * H];
    __shared__ float x[B][H];

    const int tid  = threadIdx.x;          // 0..1023
    const int warp = tid >> 5;
    const int lane = tid & 31;

    hs[tid] = g_h[tid];
    g_h[tid] = 0.0f;                       // reset for next replay
    if (tid == 0) g_ucount = 0;            // reset for next replay
    __syncthreads();

    #pragma unroll
    for (int r = 0; r < 2; r++) {
        const int j = warp + r * 32;
        const float wa = __ldg(&w1[j * H + lane]);
        const float wb = __ldg(&w1[j * H + 32 + lane]);
        const float bj = __ldg(&b1[j]);
        #pragma unroll
        for (int bb = 0; bb < B; bb++) {
            float p = hs[bb * H + lane] * wa + hs[bb * H + 32 + lane] * wb;
            p += __shfl_down_sync(0xffffffffu, p, 16);
            p += __shfl_down_sync(0xffffffffu, p, 8);
            p += __shfl_down_sync(0xffffffffu, p, 4);
            p += __shfl_down_sync(0xffffffffu, p, 2);
            p += __shfl_down_sync(0xffffffffu, p, 1);
            if (lane == 0) x[bb][j] = fmaxf(p + bj, 0.f);
        }
    }
    __syncthreads();

    if (tid < B * OUT) {
        const int bb = tid >> 1;
        const int o  = tid & 1;
        float a = __ldg(&b2[o]);
        #pragma unroll
        for (int k = 0; k < H; k++)
            a = fmaf(x[bb][k], __ldg(&w2[o * H + k]), a);
        out[bb * OUT + o] = a;
    }
}

// ---------------------------------------------------------------------------
// Launch
// Inputs (metadata order): s1, s2, embed, sos, w1, b1, w2, b2
// ---------------------------------------------------------------------------
extern "C" void kernel_launch(void* const* d_in, const int* in_sizes, int n_in,
                              void* d_out, int out_size)
{
    const int*    s1    = (const int*)   d_in[0];
    const int*    s2    = (const int*)   d_in[1];
    const float4* embed = (const float4*)d_in[2];
    const float*  sos   = (const float*) d_in[3];
    const float*  w1    = (const float*) d_in[4];
    const float*  b1    = (const float*) d_in[5];
    const float*  w2    = (const float*) d_in[6];
    const float*  b2    = (const float*) d_in[7];
    float* out = (float*)d_out;

    dedup_kernel<<<NPOS / 256, 256>>>(s1, s2);
    contract_unique_kernel<<<GRIDB, 256>>>(embed, sos);
    scatter_kernel<<<B * 8, 256>>>(s1, s2);
    mlp_kernel<<<1, 1024>>>(w1, b1, w2, b2, out);
}

// round 8
// speedup vs baseline: 1.0481x; 1.0481x over previous
#include <cuda_runtime.h>
#include <cuda_bf16.h>
#include <cstdint>

// Problem constants
#define H 64
#define B 16
#define L 512
#define OUT 2
#define V 32000
#define NPOS (2 * B * L)          // 16384 token positions
#define GRIDB 1024                // blocks for the unique-contract kernel

// Persistent device state. All zero at module load; every kernel chain
// restores the zero/neutral state before finishing, so graph replays are
// deterministic.
__device__ int   g_mark[V];           // 0/1 seen flags (cleared by kernel B)
__device__ int   g_unique[NPOS];      // compacted unique token list
__device__ int   g_ucount;            // unique count (reset by kernel D)
__device__ float g_r[V * H];          // r[tok] = sos @ M_tok   (8.2 MB)
__device__ float g_h[B * H];          // per-batch accumulators (reset by D)

// ---------------------------------------------------------------------------
// Kernel A: mark + compact unique tokens. 64 blocks x 256.
// ---------------------------------------------------------------------------
__global__ void dedup_kernel(const int* __restrict__ s1,
                             const int* __restrict__ s2)
{
    const int idx = blockIdx.x * 256 + threadIdx.x;   // 0..16383
    const int tok = (idx < B * L) ? __ldg(&s1[idx]) : __ldg(&s2[idx - B * L]);
    if (atomicExch(&g_mark[tok], 1) == 0) {
        const int p = atomicAdd(&g_ucount, 1);
        g_unique[p] = tok;
    }
}

// ---------------------------------------------------------------------------
// Kernel B: r[tok][h] = sum_w sos[w] * M_tok[w][h] for each UNIQUE token.
// R8: ONE TOKEN PER WARP, no barriers in the loop.
//   lane -> h4 = lane & 15 (float4 of output cols), p = lane >> 4 (row parity)
//   lane loads rows w = p, p+2, ..., p+62 : 32 independent LDG.128, fully
//   unrolled -> deep MLP. A warp's loads at fixed i cover rows {2i, 2i+1}
//   = 512B contiguous -> coalesced. One shfl-16 combine, 16-lane STG.128.
// Also clears g_mark for the processed token.
// ---------------------------------------------------------------------------
__global__ __launch_bounds__(256, 8)
void contract_unique_kernel(const float4* __restrict__ embed,
                            const float* __restrict__ sos)
{
    __shared__ float sos_s[H];
    const int tid  = threadIdx.x;
    if (tid < H) sos_s[tid] = __ldg(&sos[tid]);
    __syncthreads();

    const int lane = tid & 31;
    const int warp = tid >> 5;
    const int h4   = lane & 15;
    const int p    = lane >> 4;

    const int n = g_ucount;            // written by dedup_kernel (prior launch)

    for (int u = blockIdx.x * 8 + warp; u < n; u += GRIDB * 8) {
        const int tok = g_unique[u];
        const float4* M = embed + (size_t)tok * (H * H / 4);

        float4 acc = make_float4(0.f, 0.f, 0.f, 0.f);
        #pragma unroll
        for (int i = 0; i < 32; i++) {
            const int w = 2 * i + p;
            const float4 m = __ldg(&M[w * 16 + h4]);
            const float  s = sos_s[w];
            acc.x = fmaf(s, m.x, acc.x);
            acc.y = fmaf(s, m.y, acc.y);
            acc.z = fmaf(s, m.z, acc.z);
            acc.w = fmaf(s, m.w, acc.w);
        }

        // Combine the two parities: lane l (+16) hold the same h-columns.
        acc.x += __shfl_down_sync(0xffffffffu, acc.x, 16);
        acc.y += __shfl_down_sync(0xffffffffu, acc.y, 16);
        acc.z += __shfl_down_sync(0xffffffffu, acc.z, 16);
        acc.w += __shfl_down_sync(0xffffffffu, acc.w, 16);

        if (lane < 16)
            reinterpret_cast<float4*>(g_r)[tok * 16 + h4] = acc;  // 256B coalesced
        if (lane == 0) g_mark[tok] = 0;    // restore for next replay
    }
}

// ---------------------------------------------------------------------------
// Kernel C: scatter-accumulate h[b][h] += r[tok][h] over all 1024 positions
// of each batch. 128 blocks (8 per batch) x 256 threads.
// ---------------------------------------------------------------------------
__global__ __launch_bounds__(256, 8)
void scatter_kernel(const int* __restrict__ s1,
                    const int* __restrict__ s2)
{
    const int b = blockIdx.x >> 3;
    const int c = blockIdx.x & 7;
    const int g = threadIdx.x >> 6;
    const int h = threadIdx.x & 63;
    const int p0 = c * 128 + g * 32;       // positions p0 .. p0+31 in [0,1024)

    float acc = 0.f;
    #pragma unroll 8
    for (int p = p0; p < p0 + 32; p++) {
        const int tok = (p < L) ? __ldg(&s1[b * L + p])
                                : __ldg(&s2[b * L + (p - L)]);
        acc += __ldg(&g_r[tok * H + h]);
    }

    __shared__ float sacc[4][H];
    sacc[g][h] = acc;
    __syncthreads();
    if (threadIdx.x < H) {
        const float s = sacc[0][threadIdx.x] + sacc[1][threadIdx.x]
                      + sacc[2][threadIdx.x] + sacc[3][threadIdx.x];
        atomicAdd(&g_h[b * H + threadIdx.x], s);
    }
}

// ---------------------------------------------------------------------------
// Kernel D: tiny MLP, 16 BLOCKS (one per batch) so the w1 fetch + compute
// parallelizes across SMs (block 0 misses to DRAM, rest hit L2).
// Resets g_h and g_ucount for the next graph replay.
// ---------------------------------------------------------------------------
__global__ __launch_bounds__(256, 1)
void mlp_kernel(const float* __restrict__ w1,
                const float* __restrict__ b1,
                const float* __restrict__ w2,
                const float* __restrict__ b2,
                float* __restrict__ out)
{
    __shared__ float w1s[H][H + 1];       // padded -> conflict-free
    __shared__ float hs[H];
    __shared__ float part[4][H];
    __shared__ float x[H];

    const int b   = blockIdx.x;
    const int tid = threadIdx.x;          // 0..255

    #pragma unroll
    for (int idx = tid; idx < H * H; idx += 256)
        w1s[idx >> 6][idx & 63] = __ldg(&w1[idx]);
    if (tid < H) {
        hs[tid] = g_h[b * H + tid];
        g_h[b * H + tid] = 0.0f;          // reset for next replay
    }
    if (b == 0 && tid == 0) g_ucount = 0; // reset for next replay
    __syncthreads();

    const int j = tid & 63;
    const int q = tid >> 6;               // k-quarter
    float psum = 0.f;
    #pragma unroll
    for (int k = q * 16; k < q * 16 + 16; k++)
        psum = fmaf(hs[k], w1s[j][k], psum);
    part[q][j] = psum;
    __syncthreads();

    if (tid < H) {
        const float a = part[0][tid] + part[1][tid] + part[2][tid]
                      + part[3][tid] + __ldg(&b1[tid]);
        x[tid] = fmaxf(a, 0.f);
    }
    __syncthreads();

    if (tid < OUT) {
        float a = __ldg(&b2[tid]);
        #pragma unroll
        for (int k = 0; k < H; k++)
            a = fmaf(x[k], __ldg(&w2[tid * H + k]), a);
        out[b * OUT + tid] = a;
    }
}

// ---------------------------------------------------------------------------
// Launch
// Inputs (metadata order): s1, s2, embed, sos, w1, b1, w2, b2
// ---------------------------------------------------------------------------
extern "C" void kernel_launch(void* const* d_in, const int* in_sizes, int n_in,
                              void* d_out, int out_size)
{
    const int*    s1    = (const int*)   d_in[0];
    const int*    s2    = (const int*)   d_in[1];
    const float4* embed = (const float4*)d_in[2];
    const float*  sos   = (const float*) d_in[3];
    const float*  w1    = (const float*) d_in[4];
    const float*  b1    = (const float*) d_in[5];
    const float*  w2    = (const float*) d_in[6];
    const float*  b2    = (const float*) d_in[7];
    float* out = (float*)d_out;

    dedup_kernel<<<NPOS / 256, 256>>>(s1, s2);
    contract_unique_kernel<<<GRIDB, 256>>>(embed, sos);
    scatter_kernel<<<B * 8, 256>>>(s1, s2);
    mlp_kernel<<<B, 256>>>(w1, b1, w2, b2, out);
}

// round 9
// speedup vs baseline: 1.2886x; 1.2295x over previous
#include <cuda_runtime.h>
#include <cuda_bf16.h>
#include <cstdint>

// Problem constants
#define H 64
#define B 16
#define L 512
#define OUT 2
#define TOKS_PER_BLOCK 16
#define BLOCKS_PER_BATCH (2 * L / TOKS_PER_BLOCK)    // 64
#define GRID1 (B * BLOCKS_PER_BATCH)                 // 1024

// Accumulator scratch: h[b][h] = sum over 1024 tokens of sos @ M_tok.
// Zero-initialized at module load; mlp_kernel resets it after reading, so
// every graph replay sees it zeroed.
__device__ float g_h[B * H];

// ---------------------------------------------------------------------------
// Kernel 1: token gather + sos contraction + per-batch accumulation.
// R9: launch_bounds(256, 4) -> 64-reg budget so ptxas can keep ~2x the
// LDG.128s in flight (the old (256,8)=32-reg cap was throttling MLP);
// unroll 8 to batch more tokens' loads together.
// ---------------------------------------------------------------------------
__global__ __launch_bounds__(256, 4)
void gather_contract_kernel(const int* __restrict__ s1,
                            const int* __restrict__ s2,
                            const float4* __restrict__ embed,
                            const float* __restrict__ sos)
{
    const int bl  = blockIdx.x;
    const int b   = bl / BLOCKS_PER_BATCH;
    const int j0  = (bl % BLOCKS_PER_BATCH) * TOKS_PER_BLOCK;  // within [0, 1024)
    const int tid = threadIdx.x;
    const int h4  = tid & 15;
    const int wg  = tid >> 4;

    // This block's 16 tokens are entirely in s1 or entirely in s2.
    const int* sp = (j0 < L) ? (s1 + b * L + j0) : (s2 + b * L + (j0 - L));

    int toks[TOKS_PER_BLOCK];
    #pragma unroll
    for (int k = 0; k < TOKS_PER_BLOCK; k++)
        toks[k] = __ldg(&sp[k]);

    const float sw0 = __ldg(&sos[wg]);
    const float sw1 = __ldg(&sos[wg + 16]);
    const float sw2 = __ldg(&sos[wg + 32]);
    const float sw3 = __ldg(&sos[wg + 48]);

    float4 acc = make_float4(0.f, 0.f, 0.f, 0.f);

    #pragma unroll 8
    for (int k = 0; k < TOKS_PER_BLOCK; k++) {
        const float4* M = embed + (size_t)toks[k] * (H * H / 4);

        float4 m0 = __ldg(&M[(wg      ) * 16 + h4]);
        float4 m1 = __ldg(&M[(wg + 16) * 16 + h4]);
        float4 m2 = __ldg(&M[(wg + 32) * 16 + h4]);
        float4 m3 = __ldg(&M[(wg + 48) * 16 + h4]);

        acc.x = fmaf(sw0, m0.x, acc.x); acc.y = fmaf(sw0, m0.y, acc.y);
        acc.z = fmaf(sw0, m0.z, acc.z); acc.w = fmaf(sw0, m0.w, acc.w);
        acc.x = fmaf(sw1, m1.x, acc.x); acc.y = fmaf(sw1, m1.y, acc.y);
        acc.z = fmaf(sw1, m1.z, acc.z); acc.w = fmaf(sw1, m1.w, acc.w);
        acc.x = fmaf(sw2, m2.x, acc.x); acc.y = fmaf(sw2, m2.y, acc.y);
        acc.z = fmaf(sw2, m2.z, acc.z); acc.w = fmaf(sw2, m2.w, acc.w);
        acc.x = fmaf(sw3, m3.x, acc.x); acc.y = fmaf(sw3, m3.y, acc.y);
        acc.z = fmaf(sw3, m3.z, acc.z); acc.w = fmaf(sw3, m3.w, acc.w);
    }

    // Warp reduce: lane l and l+16 hold the same columns for adjacent wg rows.
    acc.x += __shfl_down_sync(0xffffffffu, acc.x, 16);
    acc.y += __shfl_down_sync(0xffffffffu, acc.y, 16);
    acc.z += __shfl_down_sync(0xffffffffu, acc.z, 16);
    acc.w += __shfl_down_sync(0xffffffffu, acc.w, 16);

    __shared__ float sh[8][H];
    const int warp = tid >> 5;
    const int lane = tid & 31;
    if (lane < 16) {
        sh[warp][lane * 4 + 0] = acc.x;
        sh[warp][lane * 4 + 1] = acc.y;
        sh[warp][lane * 4 + 2] = acc.z;
        sh[warp][lane * 4 + 3] = acc.w;
    }
    __syncthreads();
    if (tid < H) {
        float s = 0.f;
        #pragma unroll
        for (int w = 0; w < 8; w++) s += sh[w][tid];
        atomicAdd(&g_h[b * H + tid], s);
    }
}

// ---------------------------------------------------------------------------
// Kernel 2: tiny MLP, 16 blocks (one per batch) — measured 5.5us in R8.
// Resets g_h for the next graph replay.
// ---------------------------------------------------------------------------
__global__ __launch_bounds__(256, 1)
void mlp_kernel(const float* __restrict__ w1,
                const float* __restrict__ b1,
                const float* __restrict__ w2,
                const float* __restrict__ b2,
                float* __restrict__ out)
{
    __shared__ float w1s[H][H + 1];       // padded -> conflict-free
    __shared__ float hs[H];
    __shared__ float part[4][H];
    __shared__ float x[H];

    const int b   = blockIdx.x;
    const int tid = threadIdx.x;          // 0..255

    #pragma unroll
    for (int idx = tid; idx < H * H; idx += 256)
        w1s[idx >> 6][idx & 63] = __ldg(&w1[idx]);
    if (tid < H) {
        hs[tid] = g_h[b * H + tid];
        g_h[b * H + tid] = 0.0f;          // reset for next replay
    }
    __syncthreads();

    const int j = tid & 63;
    const int q = tid >> 6;               // k-quarter
    float psum = 0.f;
    #pragma unroll
    for (int k = q * 16; k < q * 16 + 16; k++)
        psum = fmaf(hs[k], w1s[j][k], psum);
    part[q][j] = psum;
    __syncthreads();

    if (tid < H) {
        const float a = part[0][tid] + part[1][tid] + part[2][tid]
                      + part[3][tid] + __ldg(&b1[tid]);
        x[tid] = fmaxf(a, 0.f);
    }
    __syncthreads();

    if (tid < OUT) {
        float a = __ldg(&b2[tid]);
        #pragma unroll
        for (int k = 0; k < H; k++)
            a = fmaf(x[k], __ldg(&w2[tid * H + k]), a);
        out[b * OUT + tid] = a;
    }
}

// ---------------------------------------------------------------------------
// Launch
// Inputs (metadata order): s1, s2, embed, sos, w1, b1, w2, b2
// ---------------------------------------------------------------------------
extern "C" void kernel_launch(void* const* d_in, const int* in_sizes, int n_in,
                              void* d_out, int out_size)
{
    const int*    s1    = (const int*)   d_in[0];
    const int*    s2    = (const int*)   d_in[1];
    const float4* embed = (const float4*)d_in[2];
    const float*  sos   = (const float*) d_in[3];
    const float*  w1    = (const float*) d_in[4];
    const float*  b1    = (const float*) d_in[5];
    const float*  w2    = (const float*) d_in[6];
    const float*  b2    = (const float*) d_in[7];
    float* out = (float*)d_out;

    gather_contract_kernel<<<GRID1, 256>>>(s1, s2, embed, sos);
    mlp_kernel<<<B, 256>>>(w1, b1, w2, b2, out);
}